// round 1
// baseline (speedup 1.0000x reference)
#include <cuda_runtime.h>
#include <math.h>

#define BB 32768
#define SS 512
#define NH1 400
#define NH2 300
#define NAOUT 8
#define NSAMP 3

// ---------------- scratch (static device globals; no allocation) ----------------
static __device__ float g_m1[(size_t)BB * NH1];                 // 52.4 MB
static __device__ float g_v1[(size_t)BB * NH1];                 // 52.4 MB
static __device__ float g_m2[(size_t)NSAMP * BB * NH2];         // 118 MB
static __device__ float g_v2[(size_t)NSAMP * BB * NH2];         // 118 MB
static __device__ unsigned g_min_u, g_max_u;
static __device__ float g_s1[NH1];   // rowsum(W1)
static __device__ float g_c1[NH1];   // 2.0001 * rowsum(W1^2)  (constant ADF variance in)

// monotonic float<->uint key for exact atomic min/max
static __device__ __forceinline__ unsigned fkey(float f) {
    unsigned u = __float_as_uint(f);
    return (u & 0x80000000u) ? ~u : (u | 0x80000000u);
}
static __device__ __forceinline__ float funkey(unsigned u) {
    return __uint_as_float((u & 0x80000000u) ? (u ^ 0x80000000u) : ~u);
}

static __device__ __forceinline__ void adf_relu(float m, float v, float &om, float &ov) {
    float sd  = sqrtf(v);
    float r   = m / sd;
    float cdf = 0.5f * (1.0f + erff(r * 0.7071067811865476f));
    float pdf = 0.3989422804014327f * expf(-0.5f * r * r);
    float o   = m * cdf + sd * pdf;
    om = o;
    ov = (m * m + v) * cdf + m * sd * pdf - o * o;
}

// ---------------- kernel 0: reset reduction state (graph-replay safe) ----------------
__global__ void k_init() {
    g_min_u = 0xFFFFFFFFu;
    g_max_u = 0u;
}

// ---------------- kernel 1: global min/max of x ----------------
__global__ __launch_bounds__(256) void k_minmax(const float4 *__restrict__ x, int n4) {
    unsigned lmin = 0xFFFFFFFFu, lmax = 0u;
    for (int i = blockIdx.x * blockDim.x + threadIdx.x; i < n4; i += gridDim.x * blockDim.x) {
        float4 v = x[i];
        unsigned k0 = fkey(v.x), k1 = fkey(v.y), k2 = fkey(v.z), k3 = fkey(v.w);
        lmin = min(lmin, min(min(k0, k1), min(k2, k3)));
        lmax = max(lmax, max(max(k0, k1), max(k2, k3)));
    }
    lmin = __reduce_min_sync(0xFFFFFFFFu, lmin);
    lmax = __reduce_max_sync(0xFFFFFFFFu, lmax);
    __shared__ unsigned smin[8], smax[8];
    int wid = threadIdx.x >> 5, lane = threadIdx.x & 31;
    if (lane == 0) { smin[wid] = lmin; smax[wid] = lmax; }
    __syncthreads();
    if (threadIdx.x == 0) {
        unsigned m = smin[0], M = smax[0];
        #pragma unroll
        for (int i = 1; i < 8; i++) { m = min(m, smin[i]); M = max(M, smax[i]); }
        atomicMin(&g_min_u, m);
        atomicMax(&g_max_u, M);
    }
}

// ---------------- kernel 2: W1 row stats ----------------
__global__ __launch_bounds__(128) void k_w1stats(const float *__restrict__ W1) {
    int h = blockIdx.x;
    const float *row = W1 + (size_t)h * SS;
    float s = 0.f, q = 0.f;
    for (int k = threadIdx.x; k < SS; k += 128) {
        float w = row[k];
        s += w;
        q += w * w;
    }
    #pragma unroll
    for (int o = 16; o; o >>= 1) {
        s += __shfl_xor_sync(0xFFFFFFFFu, s, o);
        q += __shfl_xor_sync(0xFFFFFFFFu, q, o);
    }
    __shared__ float ss[4], qq[4];
    int wid = threadIdx.x >> 5;
    if ((threadIdx.x & 31) == 0) { ss[wid] = s; qq[wid] = q; }
    __syncthreads();
    if (threadIdx.x == 0) {
        g_s1[h] = ss[0] + ss[1] + ss[2] + ss[3];
        g_c1[h] = 2.0001f * (qq[0] + qq[1] + qq[2] + qq[3]);
    }
}

// ---------------- kernel 3: GEMM1 (x @ W1^T) + affine + bias + ADF ReLU ----------------
// BM=128, BN=64, BK=16, 256 threads, TM=8, TN=4
__global__ __launch_bounds__(256) void k_gemm1(const float *__restrict__ x,
                                               const float *__restrict__ W1,
                                               const float *__restrict__ b1) {
    __shared__ float As[16 * 128];
    __shared__ float Bs[16 * 64];
    int tid = threadIdx.x;
    int tx = tid & 15, ty = tid >> 4;
    int rowBase = blockIdx.x * 128;
    int colBase = blockIdx.y * 64;

    float acc[8][4];
    #pragma unroll
    for (int i = 0; i < 8; i++)
        #pragma unroll
        for (int j = 0; j < 4; j++) acc[i][j] = 0.f;

    int ar = tid >> 2;
    int ak = (tid & 3) * 4;

    for (int k0 = 0; k0 < SS; k0 += 16) {
        float4 a0 = *(const float4 *)(x + (size_t)(rowBase + ar) * SS + k0 + ak);
        float4 a1 = *(const float4 *)(x + (size_t)(rowBase + ar + 64) * SS + k0 + ak);
        int j = colBase + ar;
        float4 b0 = make_float4(0.f, 0.f, 0.f, 0.f);
        if (j < NH1) b0 = *(const float4 *)(W1 + (size_t)j * SS + k0 + ak);
        __syncthreads();
        As[(ak + 0) * 128 + ar] = a0.x;
        As[(ak + 1) * 128 + ar] = a0.y;
        As[(ak + 2) * 128 + ar] = a0.z;
        As[(ak + 3) * 128 + ar] = a0.w;
        As[(ak + 0) * 128 + ar + 64] = a1.x;
        As[(ak + 1) * 128 + ar + 64] = a1.y;
        As[(ak + 2) * 128 + ar + 64] = a1.z;
        As[(ak + 3) * 128 + ar + 64] = a1.w;
        Bs[(ak + 0) * 64 + ar] = b0.x;
        Bs[(ak + 1) * 64 + ar] = b0.y;
        Bs[(ak + 2) * 64 + ar] = b0.z;
        Bs[(ak + 3) * 64 + ar] = b0.w;
        __syncthreads();
        #pragma unroll
        for (int kk = 0; kk < 16; kk++) {
            float4 t0 = *(float4 *)&As[kk * 128 + ty * 8];
            float4 t1 = *(float4 *)&As[kk * 128 + ty * 8 + 4];
            float4 tb = *(float4 *)&Bs[kk * 64 + tx * 4];
            float ra[8] = {t0.x, t0.y, t0.z, t0.w, t1.x, t1.y, t1.z, t1.w};
            float rb[4] = {tb.x, tb.y, tb.z, tb.w};
            #pragma unroll
            for (int i = 0; i < 8; i++)
                #pragma unroll
                for (int jj = 0; jj < 4; jj++) acc[i][jj] += ra[i] * rb[jj];
        }
    }

    float fmin = funkey(g_min_u);
    float fmax = funkey(g_max_u);
    float a_ = 1.0f / (fmax - fmin);
    float c_ = 0.1f - fmin * a_;

    int col = colBase + tx * 4;
    if (col < NH1) {
        #pragma unroll
        for (int i = 0; i < 8; i++) {
            int r = rowBase + ty * 8 + i;
            float4 om4, ov4;
            float *omp = &om4.x, *ovp = &ov4.x;
            #pragma unroll
            for (int jj = 0; jj < 4; jj++) {
                int h = col + jj;
                float m = a_ * acc[i][jj] + c_ * g_s1[h] + b1[h];
                float v = g_c1[h];
                float om, ov;
                adf_relu(m, v, om, ov);
                omp[jj] = om;
                ovp[jj] = ov;
            }
            *(float4 *)&g_m1[(size_t)r * NH1 + col] = om4;
            *(float4 *)&g_v1[(size_t)r * NH1 + col] = ov4;
        }
    }
}

// ---------------- kernel 4: GEMM2 dual (m & v) per sample + ADF + mask2 ----------------
// BM=128, BN=64, BK=16, 256 threads, TM=8, TN=4, grid.z = sample
__global__ __launch_bounds__(256) void k_gemm2(const float *__restrict__ W2,
                                               const float *__restrict__ b2,
                                               const float *__restrict__ mask1,
                                               const float *__restrict__ mask2) {
    __shared__ float Am[16 * 128];
    __shared__ float Av[16 * 128];
    __shared__ float Bs[16 * 64];
    int tid = threadIdx.x;
    int tx = tid & 15, ty = tid >> 4;
    int rowBase = blockIdx.x * 128;
    int colBase = blockIdx.y * 64;
    int n = blockIdx.z;
    const float *mkp = mask1 + (size_t)n * BB * NH1;

    float accm[8][4], accv[8][4];
    #pragma unroll
    for (int i = 0; i < 8; i++)
        #pragma unroll
        for (int j = 0; j < 4; j++) { accm[i][j] = 0.f; accv[i][j] = 0.f; }

    int ar = tid >> 2;
    int ak = (tid & 3) * 4;

    for (int k0 = 0; k0 < NH1; k0 += 16) {
        size_t o0 = (size_t)(rowBase + ar) * NH1 + k0 + ak;
        size_t o1 = (size_t)(rowBase + ar + 64) * NH1 + k0 + ak;
        float4 m0 = *(const float4 *)(g_m1 + o0);
        float4 v0 = *(const float4 *)(g_v1 + o0);
        float4 q0 = *(const float4 *)(mkp + o0);
        float4 m1r = *(const float4 *)(g_m1 + o1);
        float4 v1r = *(const float4 *)(g_v1 + o1);
        float4 q1 = *(const float4 *)(mkp + o1);
        int j = colBase + ar;
        float4 w = make_float4(0.f, 0.f, 0.f, 0.f);
        if (j < NH2) w = *(const float4 *)(W2 + (size_t)j * NH1 + k0 + ak);
        __syncthreads();
        Am[(ak + 0) * 128 + ar] = m0.x * q0.x;
        Am[(ak + 1) * 128 + ar] = m0.y * q0.y;
        Am[(ak + 2) * 128 + ar] = m0.z * q0.z;
        Am[(ak + 3) * 128 + ar] = m0.w * q0.w;
        Av[(ak + 0) * 128 + ar] = v0.x * q0.x * q0.x;
        Av[(ak + 1) * 128 + ar] = v0.y * q0.y * q0.y;
        Av[(ak + 2) * 128 + ar] = v0.z * q0.z * q0.z;
        Av[(ak + 3) * 128 + ar] = v0.w * q0.w * q0.w;
        Am[(ak + 0) * 128 + ar + 64] = m1r.x * q1.x;
        Am[(ak + 1) * 128 + ar + 64] = m1r.y * q1.y;
        Am[(ak + 2) * 128 + ar + 64] = m1r.z * q1.z;
        Am[(ak + 3) * 128 + ar + 64] = m1r.w * q1.w;
        Av[(ak + 0) * 128 + ar + 64] = v1r.x * q1.x * q1.x;
        Av[(ak + 1) * 128 + ar + 64] = v1r.y * q1.y * q1.y;
        Av[(ak + 2) * 128 + ar + 64] = v1r.z * q1.z * q1.z;
        Av[(ak + 3) * 128 + ar + 64] = v1r.w * q1.w * q1.w;
        Bs[(ak + 0) * 64 + ar] = w.x;
        Bs[(ak + 1) * 64 + ar] = w.y;
        Bs[(ak + 2) * 64 + ar] = w.z;
        Bs[(ak + 3) * 64 + ar] = w.w;
        __syncthreads();
        #pragma unroll
        for (int kk = 0; kk < 16; kk++) {
            float4 t0 = *(float4 *)&Am[kk * 128 + ty * 8];
            float4 t1 = *(float4 *)&Am[kk * 128 + ty * 8 + 4];
            float4 u0 = *(float4 *)&Av[kk * 128 + ty * 8];
            float4 u1 = *(float4 *)&Av[kk * 128 + ty * 8 + 4];
            float4 tb = *(float4 *)&Bs[kk * 64 + tx * 4];
            float ra[8] = {t0.x, t0.y, t0.z, t0.w, t1.x, t1.y, t1.z, t1.w};
            float rv[8] = {u0.x, u0.y, u0.z, u0.w, u1.x, u1.y, u1.z, u1.w};
            float rb[4] = {tb.x, tb.y, tb.z, tb.w};
            float rb2[4] = {tb.x * tb.x, tb.y * tb.y, tb.z * tb.z, tb.w * tb.w};
            #pragma unroll
            for (int i = 0; i < 8; i++)
                #pragma unroll
                for (int jj = 0; jj < 4; jj++) {
                    accm[i][jj] += ra[i] * rb[jj];
                    accv[i][jj] += rv[i] * rb2[jj];
                }
        }
    }

    int col = colBase + tx * 4;
    if (col < NH2) {
        #pragma unroll
        for (int i = 0; i < 8; i++) {
            int r = rowBase + ty * 8 + i;
            size_t base = ((size_t)n * BB + r) * NH2 + col;
            float4 mk = *(const float4 *)(mask2 + base);
            float *mkp4 = &mk.x;
            float4 om4, ov4;
            float *omp = &om4.x, *ovp = &ov4.x;
            #pragma unroll
            for (int jj = 0; jj < 4; jj++) {
                float m = accm[i][jj] + b2[col + jj];
                float v = accv[i][jj];
                float om, ov;
                adf_relu(m, v, om, ov);
                float q = mkp4[jj];
                omp[jj] = om * q;
                ovp[jj] = ov * q * q;
            }
            *(float4 *)&g_m2[base] = om4;
            *(float4 *)&g_v2[base] = ov4;
        }
    }
}

// ---------------- kernel 5: layer3 + MC statistics + 10^var ----------------
// one warp per batch row b; lanes split H2
__global__ __launch_bounds__(256) void k_final(const float *__restrict__ W3,
                                               const float *__restrict__ b3,
                                               float *__restrict__ out) {
    __shared__ float w3s[NAOUT * NH2];
    __shared__ float w3s2[NAOUT * NH2];
    __shared__ float b3s[NAOUT];
    int tid = threadIdx.x;
    for (int i = tid; i < NAOUT * NH2; i += 256) {
        float w = W3[i];
        w3s[i] = w;
        w3s2[i] = w * w;
    }
    if (tid < NAOUT) b3s[tid] = b3[tid];
    __syncthreads();

    int warp = tid >> 5, lane = tid & 31;
    size_t b = (size_t)blockIdx.x * 8 + warp;

    float am[NSAMP][NAOUT], av[NSAMP][NAOUT];
    #pragma unroll
    for (int n = 0; n < NSAMP; n++)
        #pragma unroll
        for (int a = 0; a < NAOUT; a++) { am[n][a] = 0.f; av[n][a] = 0.f; }

    for (int j = lane; j < NH2; j += 32) {
        float w[NAOUT], w2[NAOUT];
        #pragma unroll
        for (int a = 0; a < NAOUT; a++) {
            w[a] = w3s[a * NH2 + j];
            w2[a] = w3s2[a * NH2 + j];
        }
        #pragma unroll
        for (int n = 0; n < NSAMP; n++) {
            size_t off = ((size_t)n * BB + b) * NH2 + j;
            float mf = g_m2[off];
            float vf = g_v2[off];
            #pragma unroll
            for (int a = 0; a < NAOUT; a++) {
                am[n][a] += mf * w[a];
                av[n][a] += vf * w2[a];
            }
        }
    }
    #pragma unroll
    for (int n = 0; n < NSAMP; n++)
        #pragma unroll
        for (int a = 0; a < NAOUT; a++)
            #pragma unroll
            for (int o = 16; o; o >>= 1) {
                am[n][a] += __shfl_xor_sync(0xFFFFFFFFu, am[n][a], o);
                av[n][a] += __shfl_xor_sync(0xFFFFFFFFu, av[n][a], o);
            }

    if (lane == 0) {
        #pragma unroll
        for (int a = 0; a < NAOUT; a++) {
            float s1 = 0.f, s2 = 0.f, sv = 0.f;
            #pragma unroll
            for (int n = 0; n < NSAMP; n++) {
                float m3 = am[n][a] + b3s[a];
                s1 += m3;
                s2 += m3 * m3;
                sv += av[n][a];
            }
            const float inv3 = 1.0f / 3.0f;
            float mean = s1 * inv3;
            float var = sv * inv3 + s2 * inv3 - mean * mean;
            out[b * NAOUT + a] = mean;
            out[(size_t)BB * NAOUT + b * NAOUT + a] = exp10f(var);
        }
    }
}

// ---------------- launch ----------------
extern "C" void kernel_launch(void *const *d_in, const int *in_sizes, int n_in,
                              void *d_out, int out_size) {
    const float *x  = (const float *)d_in[0];
    // d_in[1] = x_noise (unused by reference)
    const float *W1 = (const float *)d_in[2];
    const float *b1 = (const float *)d_in[3];
    const float *W2 = (const float *)d_in[4];
    const float *b2 = (const float *)d_in[5];
    const float *W3 = (const float *)d_in[6];
    const float *b3 = (const float *)d_in[7];
    const float *mask1 = (const float *)d_in[8];
    const float *mask2 = (const float *)d_in[9];
    float *out = (float *)d_out;

    k_init<<<1, 1>>>();
    k_minmax<<<2048, 256>>>((const float4 *)x, BB * SS / 4);
    k_w1stats<<<NH1, 128>>>(W1);
    dim3 g1(BB / 128, (NH1 + 63) / 64);
    k_gemm1<<<g1, 256>>>(x, W1, b1);
    dim3 g2(BB / 128, (NH2 + 63) / 64, NSAMP);
    k_gemm2<<<g2, 256>>>(W2, b2, mask1, mask2);
    k_final<<<BB / 8, 256>>>(W3, b3, out);
}